// round 1
// baseline (speedup 1.0000x reference)
#include <cuda_runtime.h>

// ---------------- fixed problem shapes ----------------
constexpr int NT    = 16384;          // tokens (16*32*32)
constexpr int C     = 768;
constexpr int N2    = 2048;           // conv output tokens (8*16*16)
constexpr int KCONV = 6144;           // 768*8
constexpr int NA_Q = 14336, NB_Q = 2048, R_Q = 8192, UNM_Q = 6144, MQ = 8192;
constexpr int NA_K = 1792,  NB_K = 256,  R_K = 1024, UNM_K = 768,  MK = 1024;
constexpr int HEADS = 8, HD = 96;

// ---------------- static device scratch ----------------
__device__ float g_Xp[N2 * KCONV];        // im2col buffer
__device__ float g_xk[N2 * C];            // conv out
__device__ float g_xkln[N2 * C];          // after LN
__device__ float g_xknorm[N2 * C];        // L2-normalized LN out
__device__ float g_xn[NT * C];            // L2-normalized x
__device__ float g_scores[NA_Q * NB_Q];   // reused for kv scores
__device__ float g_vmaxq[NA_Q];
__device__ int   g_imaxq[NA_Q];
__device__ int   g_rankq[NA_Q];
__device__ float g_vmaxk[NA_K];
__device__ int   g_imaxk[NA_K];
__device__ int   g_rankk[NA_K];
__device__ int   g_a2q[NA_Q], g_b2q[NB_Q], g_a2k[NA_K], g_b2k[NB_K];
__device__ int   g_yrow[NA_Q];            // final y-row for each q a-token
__device__ float g_xq[MQ * C];
__device__ float g_cntq[NB_Q];
__device__ float g_xkv[MK * C];
__device__ float g_cntk[NB_K];
__device__ float g_qm[MQ * C];
__device__ float g_kvm[MK * 2 * C];
__device__ float g_attn[MQ * C];
__device__ float g_ym[MQ * C];

// ---------------- helpers ----------------
__device__ __forceinline__ unsigned long long sortkey(float v, int idx) {
    unsigned u = __float_as_uint(v);
    u = (u & 0x80000000u) ? ~u : (u | 0x80000000u);   // monotonic ascending
    unsigned inv = ~u;                                 // descending by value
    return ((unsigned long long)inv << 32) | (unsigned)idx;
}

// dst positions are the all-even-coordinate lattice; count of dst strictly before n
__device__ __forceinline__ int cntb_q(int z, int y, int x) {
    return ((z + 1) >> 1) * 256 +
           (((z & 1) == 0) ? (((y + 1) >> 1) * 16 + (((y & 1) == 0) ? ((x + 1) >> 1) : 0)) : 0);
}
__device__ __forceinline__ int cntb_k(int z, int y, int x) {
    return ((z + 1) >> 1) * 64 +
           (((z & 1) == 0) ? (((y + 1) >> 1) * 8 + (((y & 1) == 0) ? ((x + 1) >> 1) : 0)) : 0);
}

// ---------------- kernels ----------------
__global__ void __launch_bounds__(256) build_maps_kernel() {
    int n = blockIdx.x * 256 + threadIdx.x;
    if (n < NT) {
        int z = n >> 10, y = (n >> 5) & 31, x = n & 31;
        int cb = cntb_q(z, y, x);
        if (((z | y | x) & 1) == 0) g_b2q[cb] = n; else g_a2q[n - cb] = n;
    }
    if (n < N2) {
        int z = n >> 8, y = (n >> 4) & 15, x = n & 15;
        int cb = cntb_k(z, y, x);
        if (((z | y | x) & 1) == 0) g_b2k[cb] = n; else g_a2k[n - cb] = n;
    }
}

__global__ void __launch_bounds__(256) im2col_kernel(const float* __restrict__ x) {
    int idx = blockIdx.x * 256 + threadIdx.x;
    if (idx >= N2 * KCONV) return;
    int t = idx / KCONV, k = idx - t * KCONV;
    int ci = k >> 3, kk = k & 7;
    int zb = t >> 8, yb = (t >> 4) & 15, xb = t & 15;
    int kd = kk >> 2, kh = (kk >> 1) & 1, kw = kk & 1;
    int tok = (2 * zb + kd) * 1024 + (2 * yb + kh) * 32 + (2 * xb + kw);
    g_Xp[idx] = x[(long)tok * C + ci];
}

// C[M,N] = A[M,K] @ B[N,K]^T (+bias), optional row-gather for A and B
__global__ void __launch_bounds__(256) gemm_nt(
    const float* __restrict__ A, const int* __restrict__ rowA,
    const float* __restrict__ B, const int* __restrict__ rowB,
    float* __restrict__ Cm, const float* __restrict__ bias,
    int M, int N, int K)
{
    __shared__ float sA[16][68];
    __shared__ float sB[16][68];
    const int bm = blockIdx.y << 6;
    const int bn = blockIdx.x << 6;
    const int t  = threadIdx.x;
    const int ty4 = (t >> 4) << 2;
    const int tx4 = (t & 15) << 2;
    const int lr = t >> 2;
    const int lk = (t & 3) << 2;
    int am = bm + lr; if (am > M - 1) am = M - 1;
    int bnr = bn + lr; if (bnr > N - 1) bnr = N - 1;
    const long arow = rowA ? (long)rowA[am] : (long)am;
    const long brow = rowB ? (long)rowB[bnr] : (long)bnr;
    const float* Ap = A + arow * K + lk;
    const float* Bp = B + brow * K + lk;
    float acc[4][4];
#pragma unroll
    for (int i = 0; i < 4; i++)
#pragma unroll
        for (int j = 0; j < 4; j++) acc[i][j] = 0.f;

    for (int k0 = 0; k0 < K; k0 += 16) {
        float4 av = *reinterpret_cast<const float4*>(Ap + k0);
        float4 bv = *reinterpret_cast<const float4*>(Bp + k0);
        sA[lk + 0][lr] = av.x; sA[lk + 1][lr] = av.y; sA[lk + 2][lr] = av.z; sA[lk + 3][lr] = av.w;
        sB[lk + 0][lr] = bv.x; sB[lk + 1][lr] = bv.y; sB[lk + 2][lr] = bv.z; sB[lk + 3][lr] = bv.w;
        __syncthreads();
#pragma unroll
        for (int kk = 0; kk < 16; kk++) {
            float a0 = sA[kk][ty4 + 0], a1 = sA[kk][ty4 + 1], a2 = sA[kk][ty4 + 2], a3 = sA[kk][ty4 + 3];
            float b0 = sB[kk][tx4 + 0], b1 = sB[kk][tx4 + 1], b2 = sB[kk][tx4 + 2], b3 = sB[kk][tx4 + 3];
            acc[0][0] += a0 * b0; acc[0][1] += a0 * b1; acc[0][2] += a0 * b2; acc[0][3] += a0 * b3;
            acc[1][0] += a1 * b0; acc[1][1] += a1 * b1; acc[1][2] += a1 * b2; acc[1][3] += a1 * b3;
            acc[2][0] += a2 * b0; acc[2][1] += a2 * b1; acc[2][2] += a2 * b2; acc[2][3] += a2 * b3;
            acc[3][0] += a3 * b0; acc[3][1] += a3 * b1; acc[3][2] += a3 * b2; acc[3][3] += a3 * b3;
        }
        __syncthreads();
    }
#pragma unroll
    for (int i = 0; i < 4; i++) {
        int m = bm + ty4 + i;
        if (m >= M) continue;
        float* cp = Cm + (long)m * N;
#pragma unroll
        for (int j = 0; j < 4; j++) {
            int n = bn + tx4 + j;
            if (n < N) cp[n] = acc[i][j] + (bias ? bias[n] : 0.f);
        }
    }
}

__global__ void __launch_bounds__(256) ln_kernel(const float* __restrict__ in, float* __restrict__ out,
                                                 const float* __restrict__ gg, const float* __restrict__ bb) {
    int row = blockIdx.x;
    __shared__ float rs[256], rs2[256];
    const float* x = in + (long)row * C;
    float s = 0.f, s2 = 0.f;
    for (int c = threadIdx.x; c < C; c += 256) { float v = x[c]; s += v; s2 += v * v; }
    rs[threadIdx.x] = s; rs2[threadIdx.x] = s2;
    __syncthreads();
    for (int o = 128; o > 0; o >>= 1) {
        if (threadIdx.x < o) { rs[threadIdx.x] += rs[threadIdx.x + o]; rs2[threadIdx.x] += rs2[threadIdx.x + o]; }
        __syncthreads();
    }
    float mean = rs[0] / (float)C;
    float var = rs2[0] / (float)C - mean * mean;
    float rstd = rsqrtf(var + 1e-5f);
    for (int c = threadIdx.x; c < C; c += 256)
        out[(long)row * C + c] = (x[c] - mean) * rstd * gg[c] + bb[c];
}

__global__ void __launch_bounds__(256) rownorm_kernel(const float* __restrict__ in, float* __restrict__ out) {
    int row = blockIdx.x;
    __shared__ float rs[256];
    const float* x = in + (long)row * C;
    float s2 = 0.f;
    for (int c = threadIdx.x; c < C; c += 256) { float v = x[c]; s2 += v * v; }
    rs[threadIdx.x] = s2;
    __syncthreads();
    for (int o = 128; o > 0; o >>= 1) {
        if (threadIdx.x < o) rs[threadIdx.x] += rs[threadIdx.x + o];
        __syncthreads();
    }
    float inv = rsqrtf(rs[0]);
    for (int c = threadIdx.x; c < C; c += 256) out[(long)row * C + c] = x[c] * inv;
}

__global__ void __launch_bounds__(256) rowargmax_kernel(const float* __restrict__ S, int ncols,
                                                        float* __restrict__ vmax, int* __restrict__ imax) {
    const int row = blockIdx.x;
    __shared__ float sv[256];
    __shared__ int   si[256];
    const float* p = S + (long)row * ncols;
    float bv = -3.0e38f; int bi = 0x7FFFFFFF;
    for (int c = threadIdx.x; c < ncols; c += 256) {
        float v = p[c];
        if (v > bv) { bv = v; bi = c; }
    }
    sv[threadIdx.x] = bv; si[threadIdx.x] = bi;
    __syncthreads();
    for (int o = 128; o > 0; o >>= 1) {
        if (threadIdx.x < o) {
            float ov = sv[threadIdx.x + o]; int oi = si[threadIdx.x + o];
            if (ov > sv[threadIdx.x] || (ov == sv[threadIdx.x] && oi < si[threadIdx.x])) {
                sv[threadIdx.x] = ov; si[threadIdx.x] = oi;
            }
        }
        __syncthreads();
    }
    if (threadIdx.x == 0) { vmax[row] = sv[0]; imax[row] = si[0]; }
}

// exact rank under (value desc, index asc) total order — matches stable argsort(-v)
__global__ void __launch_bounds__(256) rank_kernel(const float* __restrict__ vals, int n, int* __restrict__ rank) {
    __shared__ unsigned long long tile[1024];
    const int i = blockIdx.x * 256 + threadIdx.x;
    unsigned long long mykey = 0xFFFFFFFFFFFFFFFFULL;
    if (i < n) mykey = sortkey(vals[i], i);
    int r = 0;
    for (int base = 0; base < n; base += 1024) {
        for (int j = threadIdx.x; j < 1024; j += 256) {
            int idx = base + j;
            tile[j] = (idx < n) ? sortkey(vals[idx], idx) : 0xFFFFFFFFFFFFFFFFULL;
        }
        __syncthreads();
        int lim = n - base; if (lim > 1024) lim = 1024;
        for (int j = 0; j < lim; j++) r += (tile[j] < mykey) ? 1 : 0;
        __syncthreads();
    }
    if (i < n) rank[i] = r;
}

// ---- q merge build ----
__global__ void __launch_bounds__(256) dstinit_q_kernel(const float* __restrict__ x) {
    int i = blockIdx.x;                           // 0..NB_Q
    const float* src = x + (long)g_b2q[i] * C;
    float* dst = g_xq + (long)(UNM_Q + i) * C;
    for (int c = threadIdx.x; c < C; c += 256) dst[c] = src[c];
    if (threadIdx.x == 0) g_cntq[i] = 1.0f;
}
__global__ void __launch_bounds__(256) scatter_q_kernel(const float* __restrict__ x) {
    int j = blockIdx.x;                           // 0..NA_Q
    const float* src = x + (long)g_a2q[j] * C;
    int r = g_rankq[j];
    if (r >= R_Q) {
        float* dst = g_xq + (long)(r - R_Q) * C;
        for (int c = threadIdx.x; c < C; c += 256) dst[c] = src[c];
        if (threadIdx.x == 0) g_yrow[j] = r - R_Q;
    } else {
        int di = g_imaxq[j];
        float* dst = g_xq + (long)(UNM_Q + di) * C;
        for (int c = threadIdx.x; c < C; c += 256) atomicAdd(&dst[c], src[c]);
        if (threadIdx.x == 0) { atomicAdd(&g_cntq[di], 1.0f); g_yrow[j] = UNM_Q + di; }
    }
}
__global__ void __launch_bounds__(256) div_q_kernel() {
    int i = blockIdx.x;
    float inv = 1.0f / g_cntq[i];
    float* dst = g_xq + (long)(UNM_Q + i) * C;
    for (int c = threadIdx.x; c < C; c += 256) dst[c] *= inv;
}

// ---- kv merge build ----
__global__ void __launch_bounds__(256) dstinit_k_kernel(const float* __restrict__ x) {
    int i = blockIdx.x;                           // 0..NB_K
    const float* src = x + (long)g_b2k[i] * C;
    float* dst = g_xkv + (long)(UNM_K + i) * C;
    for (int c = threadIdx.x; c < C; c += 256) dst[c] = src[c];
    if (threadIdx.x == 0) g_cntk[i] = 1.0f;
}
__global__ void __launch_bounds__(256) scatter_k_kernel(const float* __restrict__ x) {
    int j = blockIdx.x;                           // 0..NA_K
    const float* src = x + (long)g_a2k[j] * C;
    int r = g_rankk[j];
    if (r >= R_K) {
        float* dst = g_xkv + (long)(r - R_K) * C;
        for (int c = threadIdx.x; c < C; c += 256) dst[c] = src[c];
    } else {
        int di = g_imaxk[j];
        float* dst = g_xkv + (long)(UNM_K + di) * C;
        for (int c = threadIdx.x; c < C; c += 256) atomicAdd(&dst[c], src[c]);
        if (threadIdx.x == 0) atomicAdd(&g_cntk[di], 1.0f);
    }
}
__global__ void __launch_bounds__(256) div_k_kernel() {
    int i = blockIdx.x;
    float inv = 1.0f / g_cntk[i];
    float* dst = g_xkv + (long)(UNM_K + i) * C;
    for (int c = threadIdx.x; c < C; c += 256) dst[c] *= inv;
}

// ---- fused attention: 32 q-rows x head per block, online softmax over 32-key tiles ----
__global__ void __launch_bounds__(256) attn_kernel(const float* __restrict__ Q, const float* __restrict__ KV,
                                                   float* __restrict__ O) {
    __shared__ __align__(16) float sQ[32][96];
    __shared__ __align__(16) float sK[32][96];
    __shared__ __align__(16) float sV[32][96];
    __shared__ float sS[32][32];
    const int h = blockIdx.y;
    const int q0 = blockIdx.x * 32;
    const int t = threadIdx.x;
    const float scale = rsqrtf((float)HD);
    for (int i = t; i < 32 * 96; i += 256) {
        int r = i / 96, c = i - r * 96;
        sQ[r][c] = Q[(long)(q0 + r) * C + h * HD + c] * scale;
    }
    const int r = t >> 3;
    const int g = t & 7;
    const int c0 = g * 12;
    const int kc = g * 4;
    float m = -3.0e38f, l = 0.0f;
    float acc[12];
#pragma unroll
    for (int i = 0; i < 12; i++) acc[i] = 0.f;

    for (int kt = 0; kt < MK; kt += 32) {
        __syncthreads();
        for (int i = t; i < 32 * 96; i += 256) {
            int rr = i / 96, cc = i - rr * 96;
            sK[rr][cc] = KV[(long)(kt + rr) * (2 * C) + h * HD + cc];
            sV[rr][cc] = KV[(long)(kt + rr) * (2 * C) + C + h * HD + cc];
        }
        __syncthreads();
        const float4* q4  = reinterpret_cast<const float4*>(sQ[r]);
        const float4* k40 = reinterpret_cast<const float4*>(sK[kc + 0]);
        const float4* k41 = reinterpret_cast<const float4*>(sK[kc + 1]);
        const float4* k42 = reinterpret_cast<const float4*>(sK[kc + 2]);
        const float4* k43 = reinterpret_cast<const float4*>(sK[kc + 3]);
        float s0 = 0.f, s1 = 0.f, s2 = 0.f, s3 = 0.f;
#pragma unroll
        for (int d4 = 0; d4 < 24; d4++) {
            float4 qv = q4[d4];
            float4 a = k40[d4]; s0 += qv.x * a.x + qv.y * a.y + qv.z * a.z + qv.w * a.w;
            float4 b = k41[d4]; s1 += qv.x * b.x + qv.y * b.y + qv.z * b.z + qv.w * b.w;
            float4 c = k42[d4]; s2 += qv.x * c.x + qv.y * c.y + qv.z * c.z + qv.w * c.w;
            float4 d = k43[d4]; s3 += qv.x * d.x + qv.y * d.y + qv.z * d.z + qv.w * d.w;
        }
        float tm = fmaxf(fmaxf(s0, s1), fmaxf(s2, s3));
        tm = fmaxf(tm, __shfl_xor_sync(0xffffffffu, tm, 1));
        tm = fmaxf(tm, __shfl_xor_sync(0xffffffffu, tm, 2));
        tm = fmaxf(tm, __shfl_xor_sync(0xffffffffu, tm, 4));
        float mnew = fmaxf(m, tm);
        float corr = __expf(m - mnew);
        float p0 = __expf(s0 - mnew), p1 = __expf(s1 - mnew), p2 = __expf(s2 - mnew), p3 = __expf(s3 - mnew);
        sS[r][kc + 0] = p0; sS[r][kc + 1] = p1; sS[r][kc + 2] = p2; sS[r][kc + 3] = p3;
        float ps = p0 + p1 + p2 + p3;
        ps += __shfl_xor_sync(0xffffffffu, ps, 1);
        ps += __shfl_xor_sync(0xffffffffu, ps, 2);
        ps += __shfl_xor_sync(0xffffffffu, ps, 4);
        l = l * corr + ps;
        m = mnew;
        __syncwarp();
#pragma unroll
        for (int i = 0; i < 12; i++) acc[i] *= corr;
#pragma unroll
        for (int k = 0; k < 32; k++) {
            float p = sS[r][k];
            const float4* v4 = reinterpret_cast<const float4*>(&sV[k][c0]);
            float4 va = v4[0], vb = v4[1], vc = v4[2];
            acc[0] += p * va.x; acc[1] += p * va.y; acc[2]  += p * va.z; acc[3]  += p * va.w;
            acc[4] += p * vb.x; acc[5] += p * vb.y; acc[6]  += p * vb.z; acc[7]  += p * vb.w;
            acc[8] += p * vc.x; acc[9] += p * vc.y; acc[10] += p * vc.z; acc[11] += p * vc.w;
        }
        __syncwarp();
    }
    float invl = 1.0f / l;
    float* op = O + (long)(q0 + r) * C + h * HD + c0;
#pragma unroll
    for (int i = 0; i < 12; i++) op[i] = acc[i] * invl;
}

__global__ void __launch_bounds__(256) unmerge_kernel(float* __restrict__ out) {
    int idx = blockIdx.x * 256 + threadIdx.x;
    if (idx >= NT * C) return;
    int n = idx / C, c = idx - n * C;
    int z = n >> 10, y = (n >> 5) & 31, x = n & 31;
    int cb = cntb_q(z, y, x);
    int yrow;
    if (((z | y | x) & 1) == 0) yrow = UNM_Q + cb;
    else yrow = g_yrow[n - cb];
    out[idx] = g_ym[(long)yrow * C + c];
}

// ---------------- host ----------------
extern "C" void kernel_launch(void* const* d_in, const int* in_sizes, int n_in,
                              void* d_out, int out_size) {
    (void)in_sizes; (void)n_in; (void)out_size;
    const float* x    = (const float*)d_in[0];
    const float* sr_w = (const float*)d_in[1];
    const float* sr_b = (const float*)d_in[2];
    const float* ln_g = (const float*)d_in[3];
    const float* ln_b = (const float*)d_in[4];
    const float* Wq   = (const float*)d_in[5];
    const float* Wkv  = (const float*)d_in[6];
    const float* Wp   = (const float*)d_in[7];
    const float* bp   = (const float*)d_in[8];
    float* out = (float*)d_out;

    float *Xp, *xk, *xkln, *xknorm, *xn, *scores, *vmaxq, *vmaxk, *xq, *xkv, *qm, *kvm, *attn, *ym;
    int *imaxq, *rankq, *imaxk, *rankk, *a2q, *b2q, *a2k, *b2k;
#define SYM(p, s) cudaGetSymbolAddress((void**)&(p), s)
    SYM(Xp, g_Xp);       SYM(xk, g_xk);       SYM(xkln, g_xkln);   SYM(xknorm, g_xknorm);
    SYM(xn, g_xn);       SYM(scores, g_scores);
    SYM(vmaxq, g_vmaxq); SYM(imaxq, g_imaxq); SYM(rankq, g_rankq);
    SYM(vmaxk, g_vmaxk); SYM(imaxk, g_imaxk); SYM(rankk, g_rankk);
    SYM(a2q, g_a2q);     SYM(b2q, g_b2q);     SYM(a2k, g_a2k);     SYM(b2k, g_b2k);
    SYM(xq, g_xq);       SYM(xkv, g_xkv);
    SYM(qm, g_qm);       SYM(kvm, g_kvm);     SYM(attn, g_attn);   SYM(ym, g_ym);
#undef SYM

    build_maps_kernel<<<(NT + 255) / 256, 256>>>();
    im2col_kernel<<<(N2 * KCONV + 255) / 256, 256>>>(x);
    gemm_nt<<<dim3(C / 64, N2 / 64), 256>>>(Xp, nullptr, sr_w, nullptr, xk, sr_b, N2, C, KCONV);
    ln_kernel<<<N2, 256>>>(xk, xkln, ln_g, ln_b);
    rownorm_kernel<<<NT, 256>>>(x, xn);
    rownorm_kernel<<<N2, 256>>>(xkln, xknorm);

    // q-side matching
    gemm_nt<<<dim3(NB_Q / 64, NA_Q / 64), 256>>>(xn, a2q, xn, b2q, scores, nullptr, NA_Q, NB_Q, C);
    rowargmax_kernel<<<NA_Q, 256>>>(scores, NB_Q, vmaxq, imaxq);
    rank_kernel<<<(NA_Q + 255) / 256, 256>>>(vmaxq, NA_Q, rankq);

    // kv-side matching (reuses the scores buffer)
    gemm_nt<<<dim3(NB_K / 64, NA_K / 64), 256>>>(xknorm, a2k, xknorm, b2k, scores, nullptr, NA_K, NB_K, C);
    rowargmax_kernel<<<NA_K, 256>>>(scores, NB_K, vmaxk, imaxk);
    rank_kernel<<<(NA_K + 255) / 256, 256>>>(vmaxk, NA_K, rankk);

    // merges
    dstinit_q_kernel<<<NB_Q, 256>>>(x);
    scatter_q_kernel<<<NA_Q, 256>>>(x);
    div_q_kernel<<<NB_Q, 256>>>();
    dstinit_k_kernel<<<NB_K, 256>>>(xkln);
    scatter_k_kernel<<<NA_K, 256>>>(xkln);
    div_k_kernel<<<NB_K, 256>>>();

    // projections + attention + output projection
    gemm_nt<<<dim3(C / 64, MQ / 64), 256>>>(xq, nullptr, Wq, nullptr, qm, nullptr, MQ, C, C);
    gemm_nt<<<dim3(2 * C / 64, MK / 64), 256>>>(xkv, nullptr, Wkv, nullptr, kvm, nullptr, MK, 2 * C, C);
    attn_kernel<<<dim3(MQ / 32, HEADS), 256>>>(qm, kvm, attn);
    gemm_nt<<<dim3(C / 64, MQ / 64), 256>>>(attn, nullptr, Wp, nullptr, ym, bp, MQ, C, C);

    unmerge_kernel<<<(NT * C + 255) / 256, 256>>>(out);
}

// round 2
// speedup vs baseline: 2.7705x; 2.7705x over previous
#include <cuda_runtime.h>

// ---------------- fixed problem shapes ----------------
constexpr int NT    = 16384;          // tokens (16*32*32)
constexpr int C     = 768;
constexpr int N2    = 2048;           // conv output tokens (8*16*16)
constexpr int KCONV = 6144;           // 768*8
constexpr int NA_Q = 14336, NB_Q = 2048, R_Q = 8192, UNM_Q = 6144, MQ = 8192;
constexpr int NA_K = 1792,  NB_K = 256,  R_K = 1024, UNM_K = 768,  MK = 1024;
constexpr int HEADS = 8, HD = 96;

// ---------------- static device scratch ----------------
__device__ float g_Xp[N2 * KCONV];        // im2col buffer
__device__ float g_xk[N2 * C];            // conv out
__device__ float g_xkln[N2 * C];          // after LN
__device__ float g_xknorm[N2 * C];        // L2-normalized LN out
__device__ float g_xn[NT * C];            // L2-normalized x
__device__ float g_scores[NA_Q * NB_Q];   // reused for kv scores
__device__ float g_vmaxq[NA_Q];
__device__ int   g_imaxq[NA_Q];
__device__ int   g_rankq[NA_Q];
__device__ float g_vmaxk[NA_K];
__device__ int   g_imaxk[NA_K];
__device__ int   g_rankk[NA_K];
__device__ int   g_a2q[NA_Q], g_b2q[NB_Q], g_a2k[NA_K], g_b2k[NB_K];
__device__ int   g_yrow[NA_Q];            // final y-row for each q a-token
__device__ float g_xq[MQ * C];
__device__ float g_cntq[NB_Q];
__device__ float g_xkv[MK * C];
__device__ float g_cntk[NB_K];
__device__ float g_qm[MQ * C];
__device__ float g_kvm[MK * 2 * C];
__device__ float g_attn[MQ * C];
__device__ float g_ym[MQ * C];
__device__ float g_S[(long)HEADS * MQ * MK];   // attention scores, batched by head
__device__ float g_VT[HEADS * HD * MK];        // V transposed per head

// ---------------- helpers ----------------
__device__ __forceinline__ unsigned long long sortkey(float v, int idx) {
    unsigned u = __float_as_uint(v);
    u = (u & 0x80000000u) ? ~u : (u | 0x80000000u);   // monotonic ascending
    unsigned inv = ~u;                                 // descending by value
    return ((unsigned long long)inv << 32) | (unsigned)idx;
}

// dst positions are the all-even-coordinate lattice; count of dst strictly before n
__device__ __forceinline__ int cntb_q(int z, int y, int x) {
    return ((z + 1) >> 1) * 256 +
           (((z & 1) == 0) ? (((y + 1) >> 1) * 16 + (((y & 1) == 0) ? ((x + 1) >> 1) : 0)) : 0);
}
__device__ __forceinline__ int cntb_k(int z, int y, int x) {
    return ((z + 1) >> 1) * 64 +
           (((z & 1) == 0) ? (((y + 1) >> 1) * 8 + (((y & 1) == 0) ? ((x + 1) >> 1) : 0)) : 0);
}

// ---------------- kernels ----------------
__global__ void __launch_bounds__(256) build_maps_kernel() {
    int n = blockIdx.x * 256 + threadIdx.x;
    if (n < NT) {
        int z = n >> 10, y = (n >> 5) & 31, x = n & 31;
        int cb = cntb_q(z, y, x);
        if (((z | y | x) & 1) == 0) g_b2q[cb] = n; else g_a2q[n - cb] = n;
    }
    if (n < N2) {
        int z = n >> 8, y = (n >> 4) & 15, x = n & 15;
        int cb = cntb_k(z, y, x);
        if (((z | y | x) & 1) == 0) g_b2k[cb] = n; else g_a2k[n - cb] = n;
    }
}

__global__ void __launch_bounds__(256) im2col_kernel(const float* __restrict__ x) {
    int idx = blockIdx.x * 256 + threadIdx.x;
    if (idx >= N2 * KCONV) return;
    int t = idx / KCONV, k = idx - t * KCONV;
    int ci = k >> 3, kk = k & 7;
    int zb = t >> 8, yb = (t >> 4) & 15, xb = t & 15;
    int kd = kk >> 2, kh = (kk >> 1) & 1, kw = kk & 1;
    int tok = (2 * zb + kd) * 1024 + (2 * yb + kh) * 32 + (2 * xb + kw);
    g_Xp[idx] = x[(long)tok * C + ci];
}

// ------------- generic fast GEMM: C = alpha*(A @ B^T) + bias -------------
// A[M,K] row stride lda, B[N,K] row stride ldb, C[M,N] row stride ldc.
// Optional row-gather (rowA/rowB), optional batch via blockIdx.z + bs* offsets.
template<int BM, int BN>
__global__ void __launch_bounds__(256, 2) gemm_nt(
    const float* __restrict__ A, const int* __restrict__ rowA, int lda, long bsA,
    const float* __restrict__ B, const int* __restrict__ rowB, int ldb, long bsB,
    float* __restrict__ Cm, int ldc, long bsC,
    const float* __restrict__ bias, float alpha,
    int M, int N, int K)
{
    constexpr int RM = BM / 16, RN = BN / 16;
    constexpr int NCM = RM / 4, NCN = RN / 4;
    constexpr int AV = BM / 32;   // floats loaded per thread per slab (4 or 2)
    constexpr int BV = BN / 32;
    __shared__ float sA[2][8][BM + 4];
    __shared__ float sB[2][8][BN + 4];
    const int bz = blockIdx.z;
    const int bm = blockIdx.y * BM;
    const int bn = blockIdx.x * BN;
    const int t = threadIdx.x;
    const int tx = t & 15, ty = t >> 4;

    int a_row, a_kq;
    if constexpr (AV == 4) { a_row = t >> 1; a_kq = (t & 1) * 4; }
    else                   { a_row = t >> 2; a_kq = (t & 3) * 2; }
    int b_row, b_kq;
    if constexpr (BV == 4) { b_row = t >> 1; b_kq = (t & 1) * 4; }
    else                   { b_row = t >> 2; b_kq = (t & 3) * 2; }

    int gm = bm + a_row; if (gm > M - 1) gm = M - 1;
    int gn = bn + b_row; if (gn > N - 1) gn = N - 1;
    const long ar = rowA ? (long)rowA[gm] : (long)gm;
    const long br = rowB ? (long)rowB[gn] : (long)gn;
    const float* Ap = A + (long)bz * bsA + ar * (long)lda + a_kq;
    const float* Bp = B + (long)bz * bsB + br * (long)ldb + b_kq;

    float acc[RM][RN];
#pragma unroll
    for (int i = 0; i < RM; i++)
#pragma unroll
        for (int j = 0; j < RN; j++) acc[i][j] = 0.f;

    float ra[AV], rb[BV];
    auto fetchA = [&](int k0) {
        if constexpr (AV == 4) {
            float4 v = *reinterpret_cast<const float4*>(Ap + k0);
            ra[0] = v.x; ra[1] = v.y; ra[2] = v.z; ra[3] = v.w;
        } else {
            float2 v = *reinterpret_cast<const float2*>(Ap + k0);
            ra[0] = v.x; ra[1] = v.y;
        }
    };
    auto fetchB = [&](int k0) {
        if constexpr (BV == 4) {
            float4 v = *reinterpret_cast<const float4*>(Bp + k0);
            rb[0] = v.x; rb[1] = v.y; rb[2] = v.z; rb[3] = v.w;
        } else {
            float2 v = *reinterpret_cast<const float2*>(Bp + k0);
            rb[0] = v.x; rb[1] = v.y;
        }
    };
    auto stash = [&](int nb) {
#pragma unroll
        for (int i = 0; i < AV; i++) sA[nb][a_kq + i][a_row] = ra[i];
#pragma unroll
        for (int i = 0; i < BV; i++) sB[nb][b_kq + i][b_row] = rb[i];
    };

    fetchA(0); fetchB(0); stash(0);
    __syncthreads();
    int buf = 0;
    for (int k0 = 0; k0 < K; k0 += 8) {
        const bool nxt = (k0 + 8) < K;
        if (nxt) { fetchA(k0 + 8); fetchB(k0 + 8); }
#pragma unroll
        for (int kk = 0; kk < 8; kk++) {
            float af[RM], bf[RN];
#pragma unroll
            for (int c = 0; c < NCM; c++) {
                float4 v = *reinterpret_cast<const float4*>(&sA[buf][kk][ty * 4 + c * 64]);
                af[c * 4 + 0] = v.x; af[c * 4 + 1] = v.y; af[c * 4 + 2] = v.z; af[c * 4 + 3] = v.w;
            }
#pragma unroll
            for (int c = 0; c < NCN; c++) {
                float4 v = *reinterpret_cast<const float4*>(&sB[buf][kk][tx * 4 + c * 64]);
                bf[c * 4 + 0] = v.x; bf[c * 4 + 1] = v.y; bf[c * 4 + 2] = v.z; bf[c * 4 + 3] = v.w;
            }
#pragma unroll
            for (int i = 0; i < RM; i++)
#pragma unroll
                for (int j = 0; j < RN; j++) acc[i][j] += af[i] * bf[j];
        }
        if (nxt) {
            stash(buf ^ 1);
            __syncthreads();
            buf ^= 1;
        }
    }

#pragma unroll
    for (int cm = 0; cm < NCM; cm++)
#pragma unroll
    for (int i = 0; i < 4; i++) {
        int m = bm + ty * 4 + cm * 64 + i;
        if (m >= M) continue;
        float* cp = Cm + (long)bz * bsC + (long)m * ldc;
#pragma unroll
        for (int cn = 0; cn < NCN; cn++) {
            int n0 = bn + tx * 4 + cn * 64;
            if (n0 >= N) continue;
            float4 o;
            o.x = acc[cm * 4 + i][cn * 4 + 0] * alpha;
            o.y = acc[cm * 4 + i][cn * 4 + 1] * alpha;
            o.z = acc[cm * 4 + i][cn * 4 + 2] * alpha;
            o.w = acc[cm * 4 + i][cn * 4 + 3] * alpha;
            if (bias) {
                float4 bv = *reinterpret_cast<const float4*>(bias + n0);
                o.x += bv.x; o.y += bv.y; o.z += bv.z; o.w += bv.w;
            }
            *reinterpret_cast<float4*>(cp + n0) = o;
        }
    }
}

__global__ void __launch_bounds__(256) ln_kernel(const float* __restrict__ in, float* __restrict__ out,
                                                 const float* __restrict__ gg, const float* __restrict__ bb) {
    int row = blockIdx.x;
    __shared__ float rs[256], rs2[256];
    const float* x = in + (long)row * C;
    float s = 0.f, s2 = 0.f;
    for (int c = threadIdx.x; c < C; c += 256) { float v = x[c]; s += v; s2 += v * v; }
    rs[threadIdx.x] = s; rs2[threadIdx.x] = s2;
    __syncthreads();
    for (int o = 128; o > 0; o >>= 1) {
        if (threadIdx.x < o) { rs[threadIdx.x] += rs[threadIdx.x + o]; rs2[threadIdx.x] += rs2[threadIdx.x + o]; }
        __syncthreads();
    }
    float mean = rs[0] / (float)C;
    float var = rs2[0] / (float)C - mean * mean;
    float rstd = rsqrtf(var + 1e-5f);
    for (int c = threadIdx.x; c < C; c += 256)
        out[(long)row * C + c] = (x[c] - mean) * rstd * gg[c] + bb[c];
}

__global__ void __launch_bounds__(256) rownorm_kernel(const float* __restrict__ in, float* __restrict__ out) {
    int row = blockIdx.x;
    __shared__ float rs[256];
    const float* x = in + (long)row * C;
    float s2 = 0.f;
    for (int c = threadIdx.x; c < C; c += 256) { float v = x[c]; s2 += v * v; }
    rs[threadIdx.x] = s2;
    __syncthreads();
    for (int o = 128; o > 0; o >>= 1) {
        if (threadIdx.x < o) rs[threadIdx.x] += rs[threadIdx.x + o];
        __syncthreads();
    }
    float inv = rsqrtf(rs[0]);
    for (int c = threadIdx.x; c < C; c += 256) out[(long)row * C + c] = x[c] * inv;
}

__global__ void __launch_bounds__(256) rowargmax_kernel(const float* __restrict__ S, int ncols,
                                                        float* __restrict__ vmax, int* __restrict__ imax) {
    const int row = blockIdx.x;
    __shared__ float sv[256];
    __shared__ int   si[256];
    const float* p = S + (long)row * ncols;
    float bv = -3.0e38f; int bi = 0x7FFFFFFF;
    for (int c = threadIdx.x; c < ncols; c += 256) {
        float v = p[c];
        if (v > bv) { bv = v; bi = c; }
    }
    sv[threadIdx.x] = bv; si[threadIdx.x] = bi;
    __syncthreads();
    for (int o = 128; o > 0; o >>= 1) {
        if (threadIdx.x < o) {
            float ov = sv[threadIdx.x + o]; int oi = si[threadIdx.x + o];
            if (ov > sv[threadIdx.x] || (ov == sv[threadIdx.x] && oi < si[threadIdx.x])) {
                sv[threadIdx.x] = ov; si[threadIdx.x] = oi;
            }
        }
        __syncthreads();
    }
    if (threadIdx.x == 0) { vmax[row] = sv[0]; imax[row] = si[0]; }
}

// exact rank under (value desc, index asc) total order — matches stable argsort(-v)
__global__ void __launch_bounds__(256) rank_kernel(const float* __restrict__ vals, int n, int* __restrict__ rank) {
    __shared__ unsigned long long tile[1024];
    const int i = blockIdx.x * 256 + threadIdx.x;
    unsigned long long mykey = 0xFFFFFFFFFFFFFFFFULL;
    if (i < n) mykey = sortkey(vals[i], i);
    int r = 0;
    for (int base = 0; base < n; base += 1024) {
        for (int j = threadIdx.x; j < 1024; j += 256) {
            int idx = base + j;
            tile[j] = (idx < n) ? sortkey(vals[idx], idx) : 0xFFFFFFFFFFFFFFFFULL;
        }
        __syncthreads();
        int lim = n - base; if (lim > 1024) lim = 1024;
        for (int j = 0; j < lim; j++) r += (tile[j] < mykey) ? 1 : 0;
        __syncthreads();
    }
    if (i < n) rank[i] = r;
}

// ---- q merge build ----
__global__ void __launch_bounds__(256) dstinit_q_kernel(const float* __restrict__ x) {
    int i = blockIdx.x;
    const float* src = x + (long)g_b2q[i] * C;
    float* dst = g_xq + (long)(UNM_Q + i) * C;
    for (int c = threadIdx.x; c < C; c += 256) dst[c] = src[c];
    if (threadIdx.x == 0) g_cntq[i] = 1.0f;
}
__global__ void __launch_bounds__(256) scatter_q_kernel(const float* __restrict__ x) {
    int j = blockIdx.x;
    const float* src = x + (long)g_a2q[j] * C;
    int r = g_rankq[j];
    if (r >= R_Q) {
        float* dst = g_xq + (long)(r - R_Q) * C;
        for (int c = threadIdx.x; c < C; c += 256) dst[c] = src[c];
        if (threadIdx.x == 0) g_yrow[j] = r - R_Q;
    } else {
        int di = g_imaxq[j];
        float* dst = g_xq + (long)(UNM_Q + di) * C;
        for (int c = threadIdx.x; c < C; c += 256) atomicAdd(&dst[c], src[c]);
        if (threadIdx.x == 0) { atomicAdd(&g_cntq[di], 1.0f); g_yrow[j] = UNM_Q + di; }
    }
}
__global__ void __launch_bounds__(256) div_q_kernel() {
    int i = blockIdx.x;
    float inv = 1.0f / g_cntq[i];
    float* dst = g_xq + (long)(UNM_Q + i) * C;
    for (int c = threadIdx.x; c < C; c += 256) dst[c] *= inv;
}

// ---- kv merge build ----
__global__ void __launch_bounds__(256) dstinit_k_kernel(const float* __restrict__ x) {
    int i = blockIdx.x;
    const float* src = x + (long)g_b2k[i] * C;
    float* dst = g_xkv + (long)(UNM_K + i) * C;
    for (int c = threadIdx.x; c < C; c += 256) dst[c] = src[c];
    if (threadIdx.x == 0) g_cntk[i] = 1.0f;
}
__global__ void __launch_bounds__(256) scatter_k_kernel(const float* __restrict__ x) {
    int j = blockIdx.x;
    const float* src = x + (long)g_a2k[j] * C;
    int r = g_rankk[j];
    if (r >= R_K) {
        float* dst = g_xkv + (long)(r - R_K) * C;
        for (int c = threadIdx.x; c < C; c += 256) dst[c] = src[c];
    } else {
        int di = g_imaxk[j];
        float* dst = g_xkv + (long)(UNM_K + di) * C;
        for (int c = threadIdx.x; c < C; c += 256) atomicAdd(&dst[c], src[c]);
        if (threadIdx.x == 0) atomicAdd(&g_cntk[di], 1.0f);
    }
}
__global__ void __launch_bounds__(256) div_k_kernel() {
    int i = blockIdx.x;
    float inv = 1.0f / g_cntk[i];
    float* dst = g_xkv + (long)(UNM_K + i) * C;
    for (int c = threadIdx.x; c < C; c += 256) dst[c] *= inv;
}

// transpose V per head: g_VT[h][d][k] = kvm[k][C + h*HD + d]
__global__ void __launch_bounds__(256) vt_kernel() {
    int idx = blockIdx.x * 256 + threadIdx.x;
    if (idx >= HEADS * HD * MK) return;
    int h = idx / (HD * MK);
    int rem = idx - h * HD * MK;
    int d = rem >> 10;           // MK = 1024
    int k = rem & (MK - 1);
    g_VT[idx] = g_kvm[(long)k * (2 * C) + C + h * HD + d];
}

// row softmax over MK=1024 columns, in place
__global__ void __launch_bounds__(256) softmax_kernel(float* __restrict__ S) {
    __shared__ float rowbuf[MK];
    __shared__ float red[256];
    const int t = threadIdx.x;
    float* p = S + (long)blockIdx.x * MK;
    float mx = -3.0e38f;
    for (int c = t; c < MK; c += 256) { float v = p[c]; rowbuf[c] = v; mx = fmaxf(mx, v); }
    red[t] = mx;
    __syncthreads();
    for (int o = 128; o > 0; o >>= 1) {
        if (t < o) red[t] = fmaxf(red[t], red[t + o]);
        __syncthreads();
    }
    float smax = red[0];
    __syncthreads();
    float s = 0.f;
    for (int c = t; c < MK; c += 256) { float e = __expf(rowbuf[c] - smax); rowbuf[c] = e; s += e; }
    red[t] = s;
    __syncthreads();
    for (int o = 128; o > 0; o >>= 1) {
        if (t < o) red[t] += red[t + o];
        __syncthreads();
    }
    float inv = 1.0f / red[0];
    for (int c = t; c < MK; c += 256) p[c] = rowbuf[c] * inv;
}

__global__ void __launch_bounds__(256) unmerge_kernel(float* __restrict__ out) {
    int idx = blockIdx.x * 256 + threadIdx.x;
    if (idx >= NT * C) return;
    int n = idx / C, c = idx - n * C;
    int z = n >> 10, y = (n >> 5) & 31, x = n & 31;
    int cb = cntb_q(z, y, x);
    int yrow;
    if (((z | y | x) & 1) == 0) yrow = UNM_Q + cb;
    else yrow = g_yrow[n - cb];
    out[idx] = g_ym[(long)yrow * C + c];
}

// ---------------- host ----------------
extern "C" void kernel_launch(void* const* d_in, const int* in_sizes, int n_in,
                              void* d_out, int out_size) {
    (void)in_sizes; (void)n_in; (void)out_size;
    const float* x    = (const float*)d_in[0];
    const float* sr_w = (const float*)d_in[1];
    const float* sr_b = (const float*)d_in[2];
    const float* ln_g = (const float*)d_in[3];
    const float* ln_b = (const float*)d_in[4];
    const float* Wq   = (const float*)d_in[5];
    const float* Wkv  = (const float*)d_in[6];
    const float* Wp   = (const float*)d_in[7];
    const float* bp   = (const float*)d_in[8];
    float* out = (float*)d_out;

    float *Xp, *xk, *xkln, *xknorm, *xn, *scores, *vmaxq, *vmaxk, *xq, *xkv, *qm, *kvm, *attn, *ym, *S, *VT;
    int *imaxq, *rankq, *imaxk, *rankk, *a2q, *b2q, *a2k, *b2k;
#define SYM(p, s) cudaGetSymbolAddress((void**)&(p), s)
    SYM(Xp, g_Xp);       SYM(xk, g_xk);       SYM(xkln, g_xkln);   SYM(xknorm, g_xknorm);
    SYM(xn, g_xn);       SYM(scores, g_scores);
    SYM(vmaxq, g_vmaxq); SYM(imaxq, g_imaxq); SYM(rankq, g_rankq);
    SYM(vmaxk, g_vmaxk); SYM(imaxk, g_imaxk); SYM(rankk, g_rankk);
    SYM(a2q, g_a2q);     SYM(b2q, g_b2q);     SYM(a2k, g_a2k);     SYM(b2k, g_b2k);
    SYM(xq, g_xq);       SYM(xkv, g_xkv);
    SYM(qm, g_qm);       SYM(kvm, g_kvm);     SYM(attn, g_attn);   SYM(ym, g_ym);
    SYM(S, g_S);         SYM(VT, g_VT);
#undef SYM

    const float qk_scale = 1.0f / sqrtf((float)HD);

    build_maps_kernel<<<(NT + 255) / 256, 256>>>();
    im2col_kernel<<<(N2 * KCONV + 255) / 256, 256>>>(x);
    // conv as GEMM: [2048 x 6144] @ [768 x 6144]^T
    gemm_nt<64, 128><<<dim3(C / 128, N2 / 64), 256>>>(
        Xp, nullptr, KCONV, 0, sr_w, nullptr, KCONV, 0, xk, C, 0, sr_b, 1.f, N2, C, KCONV);
    ln_kernel<<<N2, 256>>>(xk, xkln, ln_g, ln_b);
    rownorm_kernel<<<NT, 256>>>(x, xn);
    rownorm_kernel<<<N2, 256>>>(xkln, xknorm);

    // q-side matching: scores [14336 x 2048]
    gemm_nt<128, 128><<<dim3(NB_Q / 128, NA_Q / 128), 256>>>(
        xn, a2q, C, 0, xn, b2q, C, 0, scores, NB_Q, 0, nullptr, 1.f, NA_Q, NB_Q, C);
    rowargmax_kernel<<<NA_Q, 256>>>(scores, NB_Q, vmaxq, imaxq);
    rank_kernel<<<(NA_Q + 255) / 256, 256>>>(vmaxq, NA_Q, rankq);

    // kv-side matching: scores [1792 x 256]
    gemm_nt<64, 64><<<dim3(NB_K / 64, NA_K / 64), 256>>>(
        xknorm, a2k, C, 0, xknorm, b2k, C, 0, scores, NB_K, 0, nullptr, 1.f, NA_K, NB_K, C);
    rowargmax_kernel<<<NA_K, 256>>>(scores, NB_K, vmaxk, imaxk);
    rank_kernel<<<(NA_K + 255) / 256, 256>>>(vmaxk, NA_K, rankk);

    // merges
    dstinit_q_kernel<<<NB_Q, 256>>>(x);
    scatter_q_kernel<<<NA_Q, 256>>>(x);
    div_q_kernel<<<NB_Q, 256>>>();
    dstinit_k_kernel<<<NB_K, 256>>>(xkln);
    scatter_k_kernel<<<NA_K, 256>>>(xkln);
    div_k_kernel<<<NB_K, 256>>>();

    // projections
    gemm_nt<128, 128><<<dim3(C / 128, MQ / 128), 256>>>(
        xq, nullptr, C, 0, Wq, nullptr, C, 0, qm, C, 0, nullptr, 1.f, MQ, C, C);
    gemm_nt<64, 128><<<dim3(2 * C / 128, MK / 64), 256>>>(
        xkv, nullptr, C, 0, Wkv, nullptr, C, 0, kvm, 2 * C, 0, nullptr, 1.f, MK, 2 * C, C);
    vt_kernel<<<(HEADS * HD * MK + 255) / 256, 256>>>();

    // attention as batched GEMMs: S = scale * Q K^T  (per head)
    gemm_nt<128, 128><<<dim3(MK / 128, MQ / 128, HEADS), 256>>>(
        qm, nullptr, C, HD, kvm, nullptr, 2 * C, HD, S, MK, (long)MQ * MK,
        nullptr, qk_scale, MQ, MK, HD);
    softmax_kernel<<<HEADS * MQ, 256>>>(S);
    // attn = P @ V  (B operand = V^T per head)
    gemm_nt<128, 128><<<dim3(1, MQ / 128, HEADS), 256>>>(
        S, nullptr, MK, (long)MQ * MK, VT, nullptr, MK, (long)HD * MK, attn, C, HD,
        nullptr, 1.f, MQ, HD, MK);

    // output projection + unmerge
    gemm_nt<128, 128><<<dim3(C / 128, MQ / 128), 256>>>(
        attn, nullptr, C, 0, Wp, nullptr, C, 0, ym, C, 0, bp, 1.f, MQ, C, C);
    unmerge_kernel<<<(NT * C + 255) / 256, 256>>>(out);
}